// round 4
// baseline (speedup 1.0000x reference)
#include <cuda_runtime.h>
#include <cuda_bf16.h>
#include <math.h>
#include <stdint.h>

// ---------------- problem constants ----------------
#define Bsz   4
#define Lseq  256
#define Dm    768
#define Hh    384
#define G4    1536
#define NPAIR 8
#define Mtot  1024
#define NT    12
#define ROWW  20                 // words per staged row (16 data + 4 pad) -> 80B, 16B aligned, conflict-free
#define STAGE_W 10240            // words per stage: 4 arrays * 128 rows * 20
#define SMEM_BYTES (2 * STAGE_W * 4)   // 81920

// ---------------- device scratch ----------------
__device__ __align__(16) float          g_x[Mtot * Dm];
__device__ __align__(16) __nv_bfloat16  g_Xhi[Mtot * Dm];
__device__ __align__(16) __nv_bfloat16  g_Xlo[Mtot * Dm];
__device__ __align__(16) __nv_bfloat16  g_WhhHi[(size_t)NPAIR * G4 * Hh];
__device__ __align__(16) __nv_bfloat16  g_WhhLo[(size_t)NPAIR * G4 * Hh];
__device__ __align__(16) __nv_bfloat16  g_WihHi[(size_t)NPAIR * G4 * Dm];
__device__ __align__(16) __nv_bfloat16  g_WihLo[(size_t)NPAIR * G4 * Dm];
__device__ __align__(16) float          g_bias[NPAIR * G4];
__device__ __align__(16) float          g_P[(size_t)NPAIR * Mtot * G4];
__device__ __align__(16) __nv_bfloat16  g_Hhi[2][(size_t)NPAIR * Mtot * Hh];
__device__ __align__(16) __nv_bfloat16  g_Hlo[2][(size_t)NPAIR * Mtot * Hh];
__device__ __align__(16) float          g_C[(size_t)NPAIR * Mtot * Hh];

// ---------------- helpers ----------------
#define MMA4(acc, a, b) \
    asm volatile("mma.sync.aligned.m16n8k16.row.col.f32.bf16.bf16.f32 " \
        "{%0,%1,%2,%3},{%4,%5,%6,%7},{%8,%9},{%0,%1,%2,%3};" \
        : "+f"((acc)[0]), "+f"((acc)[1]), "+f"((acc)[2]), "+f"((acc)[3]) \
        : "r"((a)[0]), "r"((a)[1]), "r"((a)[2]), "r"((a)[3]), \
          "r"((b)[0]), "r"((b)[1]))

__device__ __forceinline__ void cp16(uint32_t d, const void* s) {
    asm volatile("cp.async.ca.shared.global [%0], [%1], 16;" :: "r"(d), "l"(s));
}
__device__ __forceinline__ void cp_commit() { asm volatile("cp.async.commit_group;"); }
__device__ __forceinline__ void cp_wait1()  { asm volatile("cp.async.wait_group 1;"); }
__device__ __forceinline__ void cp_wait0()  { asm volatile("cp.async.wait_group 0;"); }

__device__ __forceinline__ uint32_t smem_u32(const void* p) {
    uint32_t a;
    asm("{ .reg .u64 t; cvta.to.shared.u64 t, %1; cvt.u32.u64 %0, t; }" : "=r"(a) : "l"(p));
    return a;
}
__device__ __forceinline__ float sigmf(float x) { return 1.f / (1.f + __expf(-x)); }
__device__ __forceinline__ float tanhfast(float x) { return 1.f - 2.f / (__expf(2.f * x) + 1.f); }

// ---------------- kernel 1: valid-scatter ----------------
__global__ void k_scatter(const float* __restrict__ seq, const int* __restrict__ valid)
{
    int b = blockIdx.x;
    __shared__ int scan[Lseq];
    __shared__ int dest[Lseq];
    int tid = threadIdx.x;
    int v = valid[b * Lseq + tid];
    scan[tid] = v;
    __syncthreads();
    for (int off = 1; off < Lseq; off <<= 1) {
        int val = (tid >= off) ? scan[tid - off] : 0;
        __syncthreads();
        scan[tid] += val;
        __syncthreads();
    }
    dest[tid] = (v == 1) ? (scan[tid] - 1) : -1;
    __syncthreads();
    float* xb = g_x + (size_t)b * Lseq * Dm;
    for (int i = tid; i < Lseq * Dm; i += 256) xb[i] = 0.f;
    __syncthreads();
    const float* sb = seq + (size_t)b * Lseq * Dm;
    for (int i = tid; i < Lseq * Dm; i += 256) {
        int l = i / Dm, d = i - l * Dm;
        int dl = dest[l];
        if (dl >= 0) xb[dl * Dm + d] = sb[i];
    }
}

// ---------------- kernel 2: split x + zero state ----------------
__global__ void k_convX()
{
    int n = Mtot * Dm;
    for (int i = blockIdx.x * 256 + threadIdx.x; i < n; i += gridDim.x * 256) {
        float v = g_x[i];
        __nv_bfloat16 hi = __float2bfloat16(v);
        g_Xhi[i] = hi;
        g_Xlo[i] = __float2bfloat16(v - __bfloat162float(hi));
    }
    size_t n2 = (size_t)NPAIR * Mtot * Hh;
    for (size_t i = (size_t)blockIdx.x * 256 + threadIdx.x; i < n2; i += (size_t)gridDim.x * 256) {
        g_Hhi[0][i] = __float2bfloat16(0.f);
        g_Hlo[0][i] = __float2bfloat16(0.f);
        g_C[i] = 0.f;
    }
}

// ---------------- kernel 3: weight conversion ----------------
// n_il = ntile*128 + hc_local*4 + gate  ->  orig n = gate*Hh + ntile*32 + hc_local
__device__ __forceinline__ int n_orig(int n_il)
{
    int ntile = n_il >> 7, nl = n_il & 127;
    return (nl & 3) * Hh + ntile * 32 + (nl >> 2);
}
__global__ void k_convW(const float* __restrict__ whf, const float* __restrict__ whb,
                        const float* __restrict__ wif, const float* __restrict__ wib,
                        const float* __restrict__ bif, const float* __restrict__ bhf,
                        const float* __restrict__ bib, const float* __restrict__ bhb)
{
    {   // W_hh, vectorized by 4 along k
        const int KQ = Hh / 4;
        size_t tot = (size_t)NPAIR * G4 * KQ;
        for (size_t i = (size_t)blockIdx.x * 256 + threadIdx.x; i < tot; i += (size_t)gridDim.x * 256) {
            int kq = (int)(i % KQ);
            size_t r = i / KQ;
            int n_il = (int)(r % G4);
            int pair = (int)(r / G4);
            int nw = pair >> 1, dir = pair & 1;
            const float* W = (dir ? whb : whf) + (size_t)nw * G4 * Hh;
            float4 v = *(const float4*)&W[(size_t)n_orig(n_il) * Hh + kq * 4];
            __nv_bfloat16 h[4], lo[4];
            float vv[4] = {v.x, v.y, v.z, v.w};
#pragma unroll
            for (int q = 0; q < 4; q++) {
                h[q] = __float2bfloat16(vv[q]);
                lo[q] = __float2bfloat16(vv[q] - __bfloat162float(h[q]));
            }
            size_t o = ((size_t)pair * G4 + n_il) * Hh + kq * 4;
            *(uint2*)&g_WhhHi[o] = *(const uint2*)h;
            *(uint2*)&g_WhhLo[o] = *(const uint2*)lo;
        }
    }
    {   // W_ih
        const int KQ = Dm / 4;
        size_t tot = (size_t)NPAIR * G4 * KQ;
        for (size_t i = (size_t)blockIdx.x * 256 + threadIdx.x; i < tot; i += (size_t)gridDim.x * 256) {
            int kq = (int)(i % KQ);
            size_t r = i / KQ;
            int n_il = (int)(r % G4);
            int pair = (int)(r / G4);
            int nw = pair >> 1, dir = pair & 1;
            const float* W = (dir ? wib : wif) + (size_t)nw * G4 * Dm;
            float4 v = *(const float4*)&W[(size_t)n_orig(n_il) * Dm + kq * 4];
            __nv_bfloat16 h[4], lo[4];
            float vv[4] = {v.x, v.y, v.z, v.w};
#pragma unroll
            for (int q = 0; q < 4; q++) {
                h[q] = __float2bfloat16(vv[q]);
                lo[q] = __float2bfloat16(vv[q] - __bfloat162float(h[q]));
            }
            size_t o = ((size_t)pair * G4 + n_il) * Dm + kq * 4;
            *(uint2*)&g_WihHi[o] = *(const uint2*)h;
            *(uint2*)&g_WihLo[o] = *(const uint2*)lo;
        }
    }
    {   // bias (interleaved)
        int tot = NPAIR * G4;
        for (int i = blockIdx.x * 256 + threadIdx.x; i < tot; i += gridDim.x * 256) {
            int n_il = i % G4, pair = i / G4;
            int nw = pair >> 1, dir = pair & 1;
            int n = n_orig(n_il);
            g_bias[i] = dir ? (bib[nw * G4 + n] + bhb[nw * G4 + n])
                            : (bif[nw * G4 + n] + bhf[nw * G4 + n]);
        }
    }
}

// ---------------- GEMM core: CTA 128x128, 4 warps (64x64 each), Kc=32, cp.async 2-stage ----
__device__ __forceinline__ void stage_load(uint32_t sbase, int sidx, int c,
                                           const __nv_bfloat16* Ah, const __nv_bfloat16* Al,
                                           const __nv_bfloat16* Bh, const __nv_bfloat16* Bl,
                                           int stride)
{
    int tid = threadIdx.x;                     // one row per thread per array
    uint32_t d = sbase + sidx * (STAGE_W * 4) + tid * 80;
    const __nv_bfloat16* pa = Ah + (size_t)tid * stride + c * 32;
    const __nv_bfloat16* pb = Al + (size_t)tid * stride + c * 32;
    const __nv_bfloat16* pc = Bh + (size_t)tid * stride + c * 32;
    const __nv_bfloat16* pd = Bl + (size_t)tid * stride + c * 32;
#pragma unroll
    for (int j = 0; j < 4; j++) cp16(d + j * 16, pa + j * 8);
#pragma unroll
    for (int j = 0; j < 4; j++) cp16(d + 10240 + j * 16, pb + j * 8);
#pragma unroll
    for (int j = 0; j < 4; j++) cp16(d + 20480 + j * 16, pc + j * 8);
#pragma unroll
    for (int j = 0; j < 4; j++) cp16(d + 30720 + j * 16, pd + j * 8);
}

__device__ __forceinline__ void gemm_run(float acc[4][8][4],
                                         const __nv_bfloat16* Ah, const __nv_bfloat16* Al,
                                         const __nv_bfloat16* Bh, const __nv_bfloat16* Bl,
                                         int stride, int nChunks,
                                         uint32_t* SW, uint32_t sbase)
{
    int tid = threadIdx.x;
    int lane = tid & 31, wid = tid >> 5;
    int g = lane >> 2, t = lane & 3;
    int wm = wid >> 1, wn = wid & 1;

    stage_load(sbase, 0, 0, Ah, Al, Bh, Bl, stride);
    cp_commit();

#pragma unroll 1
    for (int c = 0; c < nChunks; c++) {
        if (c + 1 < nChunks) {
            stage_load(sbase, (c + 1) & 1, c + 1, Ah, Al, Bh, Bl, stride);
            cp_commit();
            cp_wait1();
        } else {
            cp_wait0();
        }
        __syncthreads();
        const uint32_t* A_h = SW + (c & 1) * STAGE_W;
        const uint32_t* A_l = A_h + 2560;
        const uint32_t* B_h = A_h + 5120;
        const uint32_t* B_l = A_h + 7680;
#pragma unroll
        for (int ks = 0; ks < 2; ks++) {
            int ko = ks * 8 + t;
            uint32_t bh[8][2], bl[8][2];
#pragma unroll
            for (int nf = 0; nf < 8; nf++) {
                int rn = (wn * 64 + nf * 8 + g) * ROWW + ko;
                bh[nf][0] = B_h[rn];  bh[nf][1] = B_h[rn + 4];
                bl[nf][0] = B_l[rn];  bl[nf][1] = B_l[rn + 4];
            }
            uint32_t a[4][4];
#pragma unroll
            for (int mf = 0; mf < 4; mf++) {
                int rm = (wm * 64 + mf * 16 + g) * ROWW + ko;
                a[mf][0] = A_h[rm];            a[mf][1] = A_h[rm + 8 * ROWW];
                a[mf][2] = A_h[rm + 4];        a[mf][3] = A_h[rm + 8 * ROWW + 4];
            }
#pragma unroll
            for (int mf = 0; mf < 4; mf++)
#pragma unroll
                for (int nf = 0; nf < 8; nf++) {
                    MMA4(acc[mf][nf], a[mf], bh[nf]);
                    MMA4(acc[mf][nf], a[mf], bl[nf]);
                }
#pragma unroll
            for (int mf = 0; mf < 4; mf++) {
                int rm = (wm * 64 + mf * 16 + g) * ROWW + ko;
                a[mf][0] = A_l[rm];            a[mf][1] = A_l[rm + 8 * ROWW];
                a[mf][2] = A_l[rm + 4];        a[mf][3] = A_l[rm + 8 * ROWW + 4];
            }
#pragma unroll
            for (int mf = 0; mf < 4; mf++)
#pragma unroll
                for (int nf = 0; nf < 8; nf++)
                    MMA4(acc[mf][nf], a[mf], bh[nf]);
        }
        __syncthreads();
    }
}

// ---------------- kernel 4: input projection ----------------
__global__ __launch_bounds__(128, 2) void k_proj_t()
{
    int ntile = blockIdx.x, mtile = blockIdx.y, pair = blockIdx.z;
    extern __shared__ uint32_t SW[];
    uint32_t sbase = smem_u32(SW);

    float acc[4][8][4];
#pragma unroll
    for (int i = 0; i < 4; i++)
#pragma unroll
        for (int j = 0; j < 8; j++)
#pragma unroll
            for (int q = 0; q < 4; q++) acc[i][j][q] = 0.f;

    gemm_run(acc,
             g_Xhi + (size_t)(mtile * 128) * Dm, g_Xlo + (size_t)(mtile * 128) * Dm,
             g_WihHi + ((size_t)pair * G4 + ntile * 128) * Dm,
             g_WihLo + ((size_t)pair * G4 + ntile * 128) * Dm,
             Dm, Dm / 32, SW, sbase);

    int tid = threadIdx.x;
    int lane = tid & 31, wid = tid >> 5;
    int g = lane >> 2, t = lane & 3;
    int wm = wid >> 1, wn = wid & 1;
    int podd = t & 1;
#pragma unroll
    for (int mf = 0; mf < 4; mf++)
#pragma unroll
        for (int nf = 0; nf < 8; nf++) {
            float x = podd ? acc[mf][nf][0] : acc[mf][nf][2];
            float y = podd ? acc[mf][nf][1] : acc[mf][nf][3];
            float xr = __shfl_xor_sync(0xffffffffu, x, 1);
            float yr = __shfl_xor_sync(0xffffffffu, y, 1);
            float g0, g1, g2, g3;
            if (podd) { g0 = xr; g1 = yr; g2 = acc[mf][nf][2]; g3 = acc[mf][nf][3]; }
            else      { g0 = acc[mf][nf][0]; g1 = acc[mf][nf][1]; g2 = xr; g3 = yr; }
            int cb = wn * 64 + nf * 8 + (t & 2) * 2;
            int prow = mtile * 128 + wm * 64 + mf * 16 + g + (podd ? 8 : 0);
            float4 bz = *(const float4*)&g_bias[pair * G4 + ntile * 128 + cb];
            float4 o = {g0 + bz.x, g1 + bz.y, g2 + bz.z, g3 + bz.w};
            *(float4*)&g_P[((size_t)pair * Mtot + prow) * G4 + ntile * 128 + cb] = o;
        }
}

// ---------------- kernel 5: one LSTM step ----------------
__global__ __launch_bounds__(128, 2) void k_step_t(int s)
{
    int ntile = blockIdx.x, mtile = blockIdx.y, pair = blockIdx.z;
    int nw = pair >> 1, dir = pair & 1, w = 3 + 2 * nw;
    if (s >= w) return;
    int half = nw + 1;
    int jstep = dir ? (w - 1 - s) : s;
    int bufr = s & 1, bufw = (s + 1) & 1;

    extern __shared__ uint32_t SW[];
    uint32_t sbase = smem_u32(SW);

    float acc[4][8][4];
#pragma unroll
    for (int i = 0; i < 4; i++)
#pragma unroll
        for (int j = 0; j < 8; j++)
#pragma unroll
            for (int q = 0; q < 4; q++) acc[i][j][q] = 0.f;

    gemm_run(acc,
             g_Hhi[bufr] + ((size_t)pair * Mtot + mtile * 128) * Hh,
             g_Hlo[bufr] + ((size_t)pair * Mtot + mtile * 128) * Hh,
             g_WhhHi + ((size_t)pair * G4 + ntile * 128) * Hh,
             g_WhhLo + ((size_t)pair * G4 + ntile * 128) * Hh,
             Hh, Hh / 32, SW, sbase);

    int tid = threadIdx.x;
    int lane = tid & 31, wid = tid >> 5;
    int g = lane >> 2, t = lane & 3;
    int wm = wid >> 1, wn = wid & 1;
    int podd = t & 1;
#pragma unroll
    for (int mf = 0; mf < 4; mf++)
#pragma unroll
        for (int nf = 0; nf < 8; nf++) {
            float x = podd ? acc[mf][nf][0] : acc[mf][nf][2];
            float y = podd ? acc[mf][nf][1] : acc[mf][nf][3];
            float xr = __shfl_xor_sync(0xffffffffu, x, 1);
            float yr = __shfl_xor_sync(0xffffffffu, y, 1);
            float g0, g1, g2, g3;
            if (podd) { g0 = xr; g1 = yr; g2 = acc[mf][nf][2]; g3 = acc[mf][nf][3]; }
            else      { g0 = acc[mf][nf][0]; g1 = acc[mf][nf][1]; g2 = xr; g3 = yr; }

            int cb = wn * 64 + nf * 8 + (t & 2) * 2;       // gate base col (n_il local)
            int hcl = cb >> 2;                              // h column local (0..31)
            int mrow = wm * 64 + mf * 16 + g + (podd ? 8 : 0);
            int prow = mtile * 128 + mrow;
            int b = prow >> 8, l = prow & 255;
            int tpos = l - half + jstep;
            bool maskv = (tpos >= 0) && (tpos < Lseq);
            size_t hidx = ((size_t)pair * Mtot + prow) * Hh + ntile * 32 + hcl;
            if (maskv) {
                float4 pv = *(const float4*)&g_P[((size_t)pair * Mtot + (b << 8) + tpos) * G4
                                                 + ntile * 128 + cb];
                float gi = g0 + pv.x;
                float gf = g1 + pv.y;
                float gg = g2 + pv.z;
                float go = g3 + pv.w;
                float si = sigmf(gi), sf = sigmf(gf), so = sigmf(go);
                float tg = tanhfast(gg);
                float c_new = sf * g_C[hidx] + si * tg;
                float h_new = so * tanhfast(c_new);
                g_C[hidx] = c_new;
                __nv_bfloat16 hi = __float2bfloat16(h_new);
                g_Hhi[bufw][hidx] = hi;
                g_Hlo[bufw][hidx] = __float2bfloat16(h_new - __bfloat162float(hi));
            } else {
                g_Hhi[bufw][hidx] = g_Hhi[bufr][hidx];
                g_Hlo[bufw][hidx] = g_Hlo[bufr][hidx];
            }
        }
}

// ---------------- kernel 6: attention + residual + head ----------------
__device__ __forceinline__ float blockReduce(float v)
{
    __shared__ float sred[8];
#pragma unroll
    for (int o = 16; o > 0; o >>= 1) v += __shfl_xor_sync(0xffffffffu, v, o);
    int wid = threadIdx.x >> 5, ln = threadIdx.x & 31;
    __syncthreads();
    if (ln == 0) sred[wid] = v;
    __syncthreads();
    float r = 0.f;
    if (wid == 0) {
        r = (ln < 8) ? sred[ln] : 0.f;
#pragma unroll
        for (int o = 4; o > 0; o >>= 1) r += __shfl_xor_sync(0xffffffffu, r, o);
    }
    return r;
}

__global__ __launch_bounds__(256) void k_final(const float* __restrict__ lw,
                                               const float* __restrict__ lb,
                                               float* __restrict__ out)
{
    int p = blockIdx.x;
    int tid = threadIdx.x;
    const float* xp = g_x + (size_t)p * Dm;
    float xv[3], mv[4][3];
    __shared__ float attn_s[4];
#pragma unroll
    for (int q = 0; q < 3; q++) xv[q] = xp[tid + q * 256];

    float logits[4];
#pragma unroll
    for (int nw = 0; nw < 4; nw++) {
        size_t fo = ((size_t)(nw * 2) * Mtot + p) * Hh;
        size_t bo = ((size_t)(nw * 2 + 1) * Mtot + p) * Hh;
#pragma unroll
        for (int q = 0; q < 3; q++) {
            int d = tid + q * 256;
            float v;
            if (d < Hh)
                v = __bfloat162float(g_Hhi[1][fo + d]) + __bfloat162float(g_Hlo[1][fo + d]);
            else
                v = __bfloat162float(g_Hhi[1][bo + d - Hh]) + __bfloat162float(g_Hlo[1][bo + d - Hh]);
            mv[nw][q] = v;
        }
        float part = xv[0] * mv[nw][0] + xv[1] * mv[nw][1] + xv[2] * mv[nw][2];
        logits[nw] = blockReduce(part);
    }
    if (tid == 0) {
        float sc = rsqrtf(768.f);
        float l0 = logits[0] * sc, l1 = logits[1] * sc, l2 = logits[2] * sc, l3 = logits[3] * sc;
        float mx = fmaxf(fmaxf(l0, l1), fmaxf(l2, l3));
        float e0 = __expf(l0 - mx), e1 = __expf(l1 - mx), e2 = __expf(l2 - mx), e3 = __expf(l3 - mx);
        float inv = 1.f / (e0 + e1 + e2 + e3);
        attn_s[0] = e0 * inv; attn_s[1] = e1 * inv; attn_s[2] = e2 * inv; attn_s[3] = e3 * inv;
    }
    __syncthreads();
    float a0 = attn_s[0], a1 = attn_s[1], a2 = attn_s[2], a3 = attn_s[3];
    float ov[3];
#pragma unroll
    for (int q = 0; q < 3; q++)
        ov[q] = xv[q] + a0 * mv[0][q] + a1 * mv[1][q] + a2 * mv[2][q] + a3 * mv[3][q];

    for (int k = 0; k < 9; k++) {
        float part = 0.f;
#pragma unroll
        for (int q = 0; q < 3; q++) part += ov[q] * lw[(size_t)k * Dm + tid + q * 256];
        float tot = blockReduce(part);
        if (tid == 0) out[p * 9 + k] = tot + lb[k];
    }
}

// ---------------- launch ----------------
extern "C" void kernel_launch(void* const* d_in, const int* in_sizes, int n_in,
                              void* d_out, int out_size)
{
    const float* seq   = (const float*)d_in[0];
    const int*   valid = (const int*)d_in[1];
    const float* wif   = (const float*)d_in[2];
    const float* whf   = (const float*)d_in[3];
    const float* bif   = (const float*)d_in[4];
    const float* bhf   = (const float*)d_in[5];
    const float* wib   = (const float*)d_in[6];
    const float* whb   = (const float*)d_in[7];
    const float* bib   = (const float*)d_in[8];
    const float* bhb   = (const float*)d_in[9];
    const float* lw    = (const float*)d_in[10];
    const float* lb    = (const float*)d_in[11];
    float* out = (float*)d_out;

    cudaFuncSetAttribute(k_proj_t, cudaFuncAttributeMaxDynamicSharedMemorySize, SMEM_BYTES);
    cudaFuncSetAttribute(k_step_t, cudaFuncAttributeMaxDynamicSharedMemorySize, SMEM_BYTES);

    k_scatter<<<Bsz, 256>>>(seq, valid);
    k_convX<<<512, 256>>>();
    k_convW<<<1024, 256>>>(whf, whb, wif, wib, bif, bhf, bib, bhb);
    k_proj_t<<<dim3(NT, 8, NPAIR), 128, SMEM_BYTES>>>();
    for (int s = 0; s < 9; s++)
        k_step_t<<<dim3(NT, 8, NPAIR), 128, SMEM_BYTES>>>(s);
    k_final<<<Mtot, 256>>>(lw, lb, out);
}

// round 9
// speedup vs baseline: 1.6208x; 1.6208x over previous
#include <cuda_runtime.h>
#include <cuda_fp16.h>
#include <math.h>
#include <stdint.h>

// ---------------- problem constants ----------------
#define Bsz   4
#define Lseq  256
#define Dm    768
#define Hh    384
#define G4    1536
#define NPAIR 8
#define Mtot  1024
#define NT    12
#define STAGE_B 30720            // bytes per stage: 3 arrays * 128 rows * 80B
#define SMEM_BYTES (2 * STAGE_B) // 61440

// ---------------- device scratch ----------------
__device__ __align__(16) float   g_x[Mtot * Dm];
__device__ __align__(16) __half  g_Xhi[Mtot * Dm];
__device__ __align__(16) __half  g_Xlo[Mtot * Dm];
__device__ __align__(16) __half  g_Whh[(size_t)NPAIR * G4 * Hh];
__device__ __align__(16) __half  g_Wih[(size_t)NPAIR * G4 * Dm];
__device__ __align__(16) float   g_bias[NPAIR * G4];
__device__ __align__(16) float   g_P[(size_t)NPAIR * Mtot * G4];
__device__ __align__(16) __half  g_Hhi[2][(size_t)NPAIR * Mtot * Hh];
__device__ __align__(16) __half  g_Hlo[2][(size_t)NPAIR * Mtot * Hh];
__device__ __align__(16) float   g_C[(size_t)NPAIR * Mtot * Hh];

// ---------------- helpers ----------------
#define MMA4(acc, a, b) \
    asm volatile("mma.sync.aligned.m16n8k16.row.col.f32.f16.f16.f32 " \
        "{%0,%1,%2,%3},{%4,%5,%6,%7},{%8,%9},{%0,%1,%2,%3};" \
        : "+f"((acc)[0]), "+f"((acc)[1]), "+f"((acc)[2]), "+f"((acc)[3]) \
        : "r"((a)[0]), "r"((a)[1]), "r"((a)[2]), "r"((a)[3]), \
          "r"((b)[0]), "r"((b)[1]))

#define LDSM_X4(r0, r1, r2, r3, addr) \
    asm volatile("ldmatrix.sync.aligned.m8n8.x4.shared.b16 {%0,%1,%2,%3}, [%4];" \
        : "=r"(r0), "=r"(r1), "=r"(r2), "=r"(r3) : "r"(addr))

__device__ __forceinline__ void cp16(uint32_t d, const void* s) {
    asm volatile("cp.async.ca.shared.global [%0], [%1], 16;" :: "r"(d), "l"(s));
}
__device__ __forceinline__ void cp_commit() { asm volatile("cp.async.commit_group;"); }
__device__ __forceinline__ void cp_wait1()  { asm volatile("cp.async.wait_group 1;"); }
__device__ __forceinline__ void cp_wait0()  { asm volatile("cp.async.wait_group 0;"); }

__device__ __forceinline__ uint32_t smem_u32(const void* p) {
    uint32_t a;
    asm("{ .reg .u64 t; cvta.to.shared.u64 t, %1; cvt.u32.u64 %0, t; }" : "=r"(a) : "l"(p));
    return a;
}
__device__ __forceinline__ float sigmf(float x) { return 1.f / (1.f + __expf(-x)); }
__device__ __forceinline__ float tanhfast(float x) { return 1.f - 2.f / (__expf(2.f * x) + 1.f); }

// ---------------- kernel 1: valid-scatter ----------------
__global__ void k_scatter(const float* __restrict__ seq, const int* __restrict__ valid)
{
    int b = blockIdx.x;
    __shared__ int scan[Lseq];
    __shared__ int dest[Lseq];
    int tid = threadIdx.x;
    int v = valid[b * Lseq + tid];
    scan[tid] = v;
    __syncthreads();
    for (int off = 1; off < Lseq; off <<= 1) {
        int val = (tid >= off) ? scan[tid - off] : 0;
        __syncthreads();
        scan[tid] += val;
        __syncthreads();
    }
    dest[tid] = (v == 1) ? (scan[tid] - 1) : -1;
    __syncthreads();
    float* xb = g_x + (size_t)b * Lseq * Dm;
    for (int i = tid; i < Lseq * Dm; i += 256) xb[i] = 0.f;
    __syncthreads();
    const float* sb = seq + (size_t)b * Lseq * Dm;
    for (int i = tid; i < Lseq * Dm; i += 256) {
        int l = i / Dm, d = i - l * Dm;
        int dl = dest[l];
        if (dl >= 0) xb[dl * Dm + d] = sb[i];
    }
}

// ---------------- kernel 2: split x into fp16 hi/lo + zero state ----------------
__global__ void k_convX()
{
    int n = Mtot * Dm;
    for (int i = blockIdx.x * 256 + threadIdx.x; i < n; i += gridDim.x * 256) {
        float v = g_x[i];
        __half hi = __float2half(v);
        g_Xhi[i] = hi;
        g_Xlo[i] = __float2half(v - __half2float(hi));
    }
    size_t n2 = (size_t)NPAIR * Mtot * Hh;
    for (size_t i = (size_t)blockIdx.x * 256 + threadIdx.x; i < n2; i += (size_t)gridDim.x * 256) {
        g_Hhi[0][i] = __float2half(0.f);
        g_Hlo[0][i] = __float2half(0.f);
        g_C[i] = 0.f;
    }
}

// ---------------- kernel 3: weight conversion ----------------
// n_il = ntile*128 + hc_local*4 + gate -> orig n = gate*Hh + ntile*32 + hc_local
__device__ __forceinline__ int n_orig(int n_il)
{
    int ntile = n_il >> 7, nl = n_il & 127;
    return (nl & 3) * Hh + ntile * 32 + (nl >> 2);
}
__global__ void k_convW(const float* __restrict__ whf, const float* __restrict__ whb,
                        const float* __restrict__ wif, const float* __restrict__ wib,
                        const float* __restrict__ bif, const float* __restrict__ bhf,
                        const float* __restrict__ bib, const float* __restrict__ bhb)
{
    {   // W_hh
        const int KQ = Hh / 4;
        size_t tot = (size_t)NPAIR * G4 * KQ;
        for (size_t i = (size_t)blockIdx.x * 256 + threadIdx.x; i < tot; i += (size_t)gridDim.x * 256) {
            int kq = (int)(i % KQ);
            size_t r = i / KQ;
            int n_il = (int)(r % G4);
            int pair = (int)(r / G4);
            int nw = pair >> 1, dir = pair & 1;
            const float* W = (dir ? whb : whf) + (size_t)nw * G4 * Hh;
            float4 v = *(const float4*)&W[(size_t)n_orig(n_il) * Hh + kq * 4];
            __half h[4] = {__float2half(v.x), __float2half(v.y),
                           __float2half(v.z), __float2half(v.w)};
            *(uint2*)&g_Whh[((size_t)pair * G4 + n_il) * Hh + kq * 4] = *(const uint2*)h;
        }
    }
    {   // W_ih
        const int KQ = Dm / 4;
        size_t tot = (size_t)NPAIR * G4 * KQ;
        for (size_t i = (size_t)blockIdx.x * 256 + threadIdx.x; i < tot; i += (size_t)gridDim.x * 256) {
            int kq = (int)(i % KQ);
            size_t r = i / KQ;
            int n_il = (int)(r % G4);
            int pair = (int)(r / G4);
            int nw = pair >> 1, dir = pair & 1;
            const float* W = (dir ? wib : wif) + (size_t)nw * G4 * Dm;
            float4 v = *(const float4*)&W[(size_t)n_orig(n_il) * Dm + kq * 4];
            __half h[4] = {__float2half(v.x), __float2half(v.y),
                           __float2half(v.z), __float2half(v.w)};
            *(uint2*)&g_Wih[((size_t)pair * G4 + n_il) * Dm + kq * 4] = *(const uint2*)h;
        }
    }
    {   // bias (interleaved)
        int tot = NPAIR * G4;
        for (int i = blockIdx.x * 256 + threadIdx.x; i < tot; i += gridDim.x * 256) {
            int n_il = i % G4, pair = i / G4;
            int nw = pair >> 1, dir = pair & 1;
            int n = n_orig(n_il);
            g_bias[i] = dir ? (bib[nw * G4 + n] + bhb[nw * G4 + n])
                            : (bif[nw * G4 + n] + bhf[nw * G4 + n]);
        }
    }
}

// ---------------- GEMM core: CTA 128x128, 8 warps (64x32 each), Kc=32 -------
// stage layout (per stage, 30720B): A_h[128][32] @+0, A_l @+10240, B @+20480.
// row stride 80B (64B data + 16B pad) -> conflict-free for LDSM and cp.async.
__device__ __forceinline__ void stage_load3(uint32_t sbase, int sidx, int c,
                                            const __half* Ah, const __half* Al,
                                            const __half* B, int stride)
{
    int tid = threadIdx.x;
    int row = tid >> 1, hf = tid & 1;
    uint32_t d = sbase + sidx * STAGE_B + row * 80 + hf * 32;
    const __half* pa = Ah + (size_t)row * stride + c * 32 + hf * 16;
    const __half* pb = Al + (size_t)row * stride + c * 32 + hf * 16;
    const __half* pc = B + (size_t)row * stride + c * 32 + hf * 16;
    cp16(d, pa);           cp16(d + 16, pa + 8);
    cp16(d + 10240, pb);   cp16(d + 10256, pb + 8);
    cp16(d + 20480, pc);   cp16(d + 20496, pc + 8);
}

__device__ __forceinline__ void gemm_run(float acc[4][4][4],
                                         const __half* Ah, const __half* Al,
                                         const __half* B, int stride, int nChunks,
                                         uint32_t sbase)
{
    int tid = threadIdx.x;
    int lane = tid & 31, wid = tid >> 5;
    int wm = wid >> 2, wn = wid & 3;

    uint32_t aoff[4], boff[2];
    int arow = (lane & 7) + ((lane >> 3) & 1) * 8;
    int ak = (lane >> 4) * 16;
#pragma unroll
    for (int mf = 0; mf < 4; mf++)
        aoff[mf] = (uint32_t)((wm * 64 + mf * 16 + arow) * 80 + ak);
    int brow = (lane & 7) + ((lane >> 4) & 1) * 8;
    int bk = ((lane >> 3) & 1) * 16;
#pragma unroll
    for (int j = 0; j < 2; j++)
        boff[j] = (uint32_t)((wn * 32 + j * 16 + brow) * 80 + bk);

    stage_load3(sbase, 0, 0, Ah, Al, B, stride);
    cp_commit();

#pragma unroll 1
    for (int c = 0; c < nChunks; c++) {
        if (c + 1 < nChunks) {
            stage_load3(sbase, (c + 1) & 1, c + 1, Ah, Al, B, stride);
            cp_commit();
            cp_wait1();
        } else {
            cp_wait0();
        }
        __syncthreads();
        uint32_t sA = sbase + (c & 1) * STAGE_B;
        uint32_t sAl = sA + 10240;
        uint32_t sB = sA + 20480;
#pragma unroll
        for (int ks = 0; ks < 2; ks++) {
            uint32_t kb = ks * 32;
            uint32_t b[4][2];
            LDSM_X4(b[0][0], b[0][1], b[1][0], b[1][1], sB + boff[0] + kb);
            LDSM_X4(b[2][0], b[2][1], b[3][0], b[3][1], sB + boff[1] + kb);
#pragma unroll
            for (int mf = 0; mf < 4; mf++) {
                uint32_t a[4];
                LDSM_X4(a[0], a[1], a[2], a[3], sA + aoff[mf] + kb);
#pragma unroll
                for (int nf = 0; nf < 4; nf++) MMA4(acc[mf][nf], a, b[nf]);
                LDSM_X4(a[0], a[1], a[2], a[3], sAl + aoff[mf] + kb);
#pragma unroll
                for (int nf = 0; nf < 4; nf++) MMA4(acc[mf][nf], a, b[nf]);
            }
        }
        __syncthreads();
    }
}

// ---------------- kernel 4: input projection ----------------
__global__ __launch_bounds__(256, 2) void k_proj_t()
{
    int ntile = blockIdx.x, mtile = blockIdx.y, pair = blockIdx.z;
    extern __shared__ uint32_t SW[];
    uint32_t sbase = smem_u32(SW);

    float acc[4][4][4];
#pragma unroll
    for (int i = 0; i < 4; i++)
#pragma unroll
        for (int j = 0; j < 4; j++)
#pragma unroll
            for (int q = 0; q < 4; q++) acc[i][j][q] = 0.f;

    gemm_run(acc,
             g_Xhi + (size_t)(mtile * 128) * Dm, g_Xlo + (size_t)(mtile * 128) * Dm,
             g_Wih + ((size_t)pair * G4 + ntile * 128) * Dm,
             Dm, Dm / 32, sbase);

    int tid = threadIdx.x;
    int lane = tid & 31, wid = tid >> 5;
    int g = lane >> 2, t = lane & 3;
    int wm = wid >> 2, wn = wid & 3;
    int podd = t & 1;
#pragma unroll
    for (int mf = 0; mf < 4; mf++)
#pragma unroll
        for (int nf = 0; nf < 4; nf++) {
            float x = podd ? acc[mf][nf][0] : acc[mf][nf][2];
            float y = podd ? acc[mf][nf][1] : acc[mf][nf][3];
            float xr = __shfl_xor_sync(0xffffffffu, x, 1);
            float yr = __shfl_xor_sync(0xffffffffu, y, 1);
            float g0, g1, g2, g3;
            if (podd) { g0 = xr; g1 = yr; g2 = acc[mf][nf][2]; g3 = acc[mf][nf][3]; }
            else      { g0 = acc[mf][nf][0]; g1 = acc[mf][nf][1]; g2 = xr; g3 = yr; }
            int cb = wn * 32 + nf * 8 + (t & 2) * 2;
            int prow = mtile * 128 + wm * 64 + mf * 16 + g + (podd ? 8 : 0);
            float4 bz = *(const float4*)&g_bias[pair * G4 + ntile * 128 + cb];
            float4 o = {g0 + bz.x, g1 + bz.y, g2 + bz.z, g3 + bz.w};
            *(float4*)&g_P[((size_t)pair * Mtot + prow) * G4 + ntile * 128 + cb] = o;
        }
}

// ---------------- kernel 5: one LSTM step ----------------
__global__ __launch_bounds__(256, 2) void k_step_t(int s)
{
    int ntile = blockIdx.x, mtile = blockIdx.y, pair = blockIdx.z;
    int nw = pair >> 1, dir = pair & 1, w = 3 + 2 * nw;
    if (s >= w) return;
    int half = nw + 1;
    int jstep = dir ? (w - 1 - s) : s;
    int bufr = s & 1, bufw = (s + 1) & 1;

    extern __shared__ uint32_t SW[];
    uint32_t sbase = smem_u32(SW);

    float acc[4][4][4];
#pragma unroll
    for (int i = 0; i < 4; i++)
#pragma unroll
        for (int j = 0; j < 4; j++)
#pragma unroll
            for (int q = 0; q < 4; q++) acc[i][j][q] = 0.f;

    gemm_run(acc,
             g_Hhi[bufr] + ((size_t)pair * Mtot + mtile * 128) * Hh,
             g_Hlo[bufr] + ((size_t)pair * Mtot + mtile * 128) * Hh,
             g_Whh + ((size_t)pair * G4 + ntile * 128) * Hh,
             Hh, Hh / 32, sbase);

    int tid = threadIdx.x;
    int lane = tid & 31, wid = tid >> 5;
    int g = lane >> 2, t = lane & 3;
    int wm = wid >> 2, wn = wid & 3;
    int podd = t & 1;
#pragma unroll
    for (int mf = 0; mf < 4; mf++)
#pragma unroll
        for (int nf = 0; nf < 4; nf++) {
            float x = podd ? acc[mf][nf][0] : acc[mf][nf][2];
            float y = podd ? acc[mf][nf][1] : acc[mf][nf][3];
            float xr = __shfl_xor_sync(0xffffffffu, x, 1);
            float yr = __shfl_xor_sync(0xffffffffu, y, 1);
            float g0, g1, g2, g3;
            if (podd) { g0 = xr; g1 = yr; g2 = acc[mf][nf][2]; g3 = acc[mf][nf][3]; }
            else      { g0 = acc[mf][nf][0]; g1 = acc[mf][nf][1]; g2 = xr; g3 = yr; }

            int cb = wn * 32 + nf * 8 + (t & 2) * 2;
            int hcl = cb >> 2;
            int mrow = wm * 64 + mf * 16 + g + (podd ? 8 : 0);
            int prow = mtile * 128 + mrow;
            int b = prow >> 8, l = prow & 255;
            int tpos = l - half + jstep;
            bool maskv = (tpos >= 0) && (tpos < Lseq);
            size_t hidx = ((size_t)pair * Mtot + prow) * Hh + ntile * 32 + hcl;
            if (maskv) {
                float4 pv = *(const float4*)&g_P[((size_t)pair * Mtot + (b << 8) + tpos) * G4
                                                 + ntile * 128 + cb];
                float gi = g0 + pv.x;
                float gf = g1 + pv.y;
                float gg = g2 + pv.z;
                float go = g3 + pv.w;
                float si = sigmf(gi), sf = sigmf(gf), so = sigmf(go);
                float tg = tanhfast(gg);
                float c_new = sf * g_C[hidx] + si * tg;
                float h_new = so * tanhfast(c_new);
                g_C[hidx] = c_new;
                __half hi = __float2half(h_new);
                g_Hhi[bufw][hidx] = hi;
                g_Hlo[bufw][hidx] = __float2half(h_new - __half2float(hi));
            } else {
                g_Hhi[bufw][hidx] = g_Hhi[bufr][hidx];
                g_Hlo[bufw][hidx] = g_Hlo[bufr][hidx];
            }
        }
}

// ---------------- kernel 6: attention + residual + head ----------------
__device__ __forceinline__ float blockReduce(float v)
{
    __shared__ float sred[8];
#pragma unroll
    for (int o = 16; o > 0; o >>= 1) v += __shfl_xor_sync(0xffffffffu, v, o);
    int wid = threadIdx.x >> 5, ln = threadIdx.x & 31;
    __syncthreads();
    if (ln == 0) sred[wid] = v;
    __syncthreads();
    float r = 0.f;
    if (wid == 0) {
        r = (ln < 8) ? sred[ln] : 0.f;
#pragma unroll
        for (int o = 4; o > 0; o >>= 1) r += __shfl_xor_sync(0xffffffffu, r, o);
    }
    return r;
}

__global__ __launch_bounds__(256) void k_final(const float* __restrict__ lw,
                                               const float* __restrict__ lb,
                                               float* __restrict__ out)
{
    int p = blockIdx.x;
    int tid = threadIdx.x;
    const float* xp = g_x + (size_t)p * Dm;
    float xv[3], mv[4][3];
    __shared__ float attn_s[4];
#pragma unroll
    for (int q = 0; q < 3; q++) xv[q] = xp[tid + q * 256];

    float logits[4];
#pragma unroll
    for (int nw = 0; nw < 4; nw++) {
        size_t fo = ((size_t)(nw * 2) * Mtot + p) * Hh;
        size_t bo = ((size_t)(nw * 2 + 1) * Mtot + p) * Hh;
#pragma unroll
        for (int q = 0; q < 3; q++) {
            int d = tid + q * 256;
            float v;
            if (d < Hh)
                v = __half2float(g_Hhi[1][fo + d]) + __half2float(g_Hlo[1][fo + d]);
            else
                v = __half2float(g_Hhi[1][bo + d - Hh]) + __half2float(g_Hlo[1][bo + d - Hh]);
            mv[nw][q] = v;
        }
        float part = xv[0] * mv[nw][0] + xv[1] * mv[nw][1] + xv[2] * mv[nw][2];
        logits[nw] = blockReduce(part);
    }
    if (tid == 0) {
        float sc = rsqrtf(768.f);
        float l0 = logits[0] * sc, l1 = logits[1] * sc, l2 = logits[2] * sc, l3 = logits[3] * sc;
        float mx = fmaxf(fmaxf(l0, l1), fmaxf(l2, l3));
        float e0 = __expf(l0 - mx), e1 = __expf(l1 - mx), e2 = __expf(l2 - mx), e3 = __expf(l3 - mx);
        float inv = 1.f / (e0 + e1 + e2 + e3);
        attn_s[0] = e0 * inv; attn_s[1] = e1 * inv; attn_s[2] = e2 * inv; attn_s[3] = e3 * inv;
    }
    __syncthreads();
    float a0 = attn_s[0], a1 = attn_s[1], a2 = attn_s[2], a3 = attn_s[3];
    float ov[3];
#pragma unroll
    for (int q = 0; q < 3; q++)
        ov[q] = xv[q] + a0 * mv[0][q] + a1 * mv[1][q] + a2 * mv[2][q] + a3 * mv[3][q];

    for (int k = 0; k < 9; k++) {
        float part = 0.f;
#pragma unroll
        for (int q = 0; q < 3; q++) part += ov[q] * lw[(size_t)k * Dm + tid + q * 256];
        float tot = blockReduce(part);
        if (tid == 0) out[p * 9 + k] = tot + lb[k];
    }
}

// ---------------- launch ----------------
extern "C" void kernel_launch(void* const* d_in, const int* in_sizes, int n_in,
                              void* d_out, int out_size)
{
    const float* seq   = (const float*)d_in[0];
    const int*   valid = (const int*)d_in[1];
    const float* wif   = (const float*)d_in[2];
    const float* whf   = (const float*)d_in[3];
    const float* bif   = (const float*)d_in[4];
    const float* bhf   = (const float*)d_in[5];
    const float* wib   = (const float*)d_in[6];
    const float* whb   = (const float*)d_in[7];
    const float* bib   = (const float*)d_in[8];
    const float* bhb   = (const float*)d_in[9];
    const float* lw    = (const float*)d_in[10];
    const float* lb    = (const float*)d_in[11];
    float* out = (float*)d_out;

    cudaFuncSetAttribute(k_proj_t, cudaFuncAttributeMaxDynamicSharedMemorySize, SMEM_BYTES);
    cudaFuncSetAttribute(k_step_t, cudaFuncAttributeMaxDynamicSharedMemorySize, SMEM_BYTES);

    k_scatter<<<Bsz, 256>>>(seq, valid);
    k_convX<<<512, 256>>>();
    k_convW<<<1024, 256>>>(whf, whb, wif, wib, bif, bhf, bib, bhb);
    k_proj_t<<<dim3(NT, 8, NPAIR), 256, SMEM_BYTES>>>();
    for (int s = 0; s < 9; s++)
        k_step_t<<<dim3(NT, 8, NPAIR), 256, SMEM_BYTES>>>(s);
    k_final<<<Mtot, 256>>>(lw, lb, out);
}

// round 10
// speedup vs baseline: 2.0996x; 1.2954x over previous
#include <cuda_runtime.h>
#include <cuda_fp16.h>
#include <math.h>
#include <stdint.h>

// ---------------- problem constants ----------------
#define Bsz   4
#define Lseq  256
#define Dm    768
#define Hh    384
#define G4    1536
#define NPAIR 8
#define Mtot  1024
#define NT    12
#define STAGE_B 20480            // bytes per stage: 2 arrays * 128 rows * 80B
#define SMEM_BYTES (3 * STAGE_B) // 61440, 3-stage pipeline

// ---------------- device scratch ----------------
__device__ __align__(16) float   g_x[Mtot * Dm];
__device__ __align__(16) __half  g_X[Mtot * Dm];
__device__ __align__(16) __half  g_Whh[(size_t)NPAIR * G4 * Hh];
__device__ __align__(16) __half  g_Wih[(size_t)NPAIR * G4 * Dm];
__device__ __align__(16) float   g_bias[NPAIR * G4];
__device__ __align__(16) float   g_P[(size_t)NPAIR * Mtot * G4];
__device__ __align__(16) __half  g_H[2][(size_t)NPAIR * Mtot * Hh];
__device__ __align__(16) float   g_C[(size_t)NPAIR * Mtot * Hh];

// ---------------- helpers ----------------
#define MMA4(acc, a, b) \
    asm volatile("mma.sync.aligned.m16n8k16.row.col.f32.f16.f16.f32 " \
        "{%0,%1,%2,%3},{%4,%5,%6,%7},{%8,%9},{%0,%1,%2,%3};" \
        : "+f"((acc)[0]), "+f"((acc)[1]), "+f"((acc)[2]), "+f"((acc)[3]) \
        : "r"((a)[0]), "r"((a)[1]), "r"((a)[2]), "r"((a)[3]), \
          "r"((b)[0]), "r"((b)[1]))

#define LDSM_X4(r0, r1, r2, r3, addr) \
    asm volatile("ldmatrix.sync.aligned.m8n8.x4.shared.b16 {%0,%1,%2,%3}, [%4];" \
        : "=r"(r0), "=r"(r1), "=r"(r2), "=r"(r3) : "r"(addr))

__device__ __forceinline__ void cp16(uint32_t d, const void* s) {
    asm volatile("cp.async.ca.shared.global [%0], [%1], 16;" :: "r"(d), "l"(s));
}
__device__ __forceinline__ void cp_commit() { asm volatile("cp.async.commit_group;"); }
__device__ __forceinline__ void cp_wait2()  { asm volatile("cp.async.wait_group 2;"); }
__device__ __forceinline__ void cp_wait1()  { asm volatile("cp.async.wait_group 1;"); }
__device__ __forceinline__ void cp_wait0()  { asm volatile("cp.async.wait_group 0;"); }

__device__ __forceinline__ uint32_t smem_u32(const void* p) {
    uint32_t a;
    asm("{ .reg .u64 t; cvta.to.shared.u64 t, %1; cvt.u32.u64 %0, t; }" : "=r"(a) : "l"(p));
    return a;
}
__device__ __forceinline__ float sigmf(float x) { return 1.f / (1.f + __expf(-x)); }
__device__ __forceinline__ float tanhfast(float x) { return 1.f - 2.f / (__expf(2.f * x) + 1.f); }

// ---------------- kernel 1: valid-scatter ----------------
__global__ void k_scatter(const float* __restrict__ seq, const int* __restrict__ valid)
{
    int b = blockIdx.x;
    __shared__ int scan[Lseq];
    __shared__ int dest[Lseq];
    int tid = threadIdx.x;
    int v = valid[b * Lseq + tid];
    scan[tid] = v;
    __syncthreads();
    for (int off = 1; off < Lseq; off <<= 1) {
        int val = (tid >= off) ? scan[tid - off] : 0;
        __syncthreads();
        scan[tid] += val;
        __syncthreads();
    }
    dest[tid] = (v == 1) ? (scan[tid] - 1) : -1;
    __syncthreads();
    float* xb = g_x + (size_t)b * Lseq * Dm;
    for (int i = tid; i < Lseq * Dm; i += 256) xb[i] = 0.f;
    __syncthreads();
    const float* sb = seq + (size_t)b * Lseq * Dm;
    for (int i = tid; i < Lseq * Dm; i += 256) {
        int l = i / Dm, d = i - l * Dm;
        int dl = dest[l];
        if (dl >= 0) xb[dl * Dm + d] = sb[i];
    }
}

// ---------------- kernel 2: convert x to fp16 + zero state ----------------
__global__ void k_convX()
{
    int n = Mtot * Dm;
    for (int i = blockIdx.x * 256 + threadIdx.x; i < n; i += gridDim.x * 256)
        g_X[i] = __float2half(g_x[i]);
    size_t n2 = (size_t)NPAIR * Mtot * Hh;
    for (size_t i = (size_t)blockIdx.x * 256 + threadIdx.x; i < n2; i += (size_t)gridDim.x * 256) {
        g_H[0][i] = __float2half(0.f);
        g_C[i] = 0.f;
    }
}

// ---------------- kernel 3: weight conversion ----------------
// n_il = ntile*128 + hc_local*4 + gate -> orig n = gate*Hh + ntile*32 + hc_local
__device__ __forceinline__ int n_orig(int n_il)
{
    int ntile = n_il >> 7, nl = n_il & 127;
    return (nl & 3) * Hh + ntile * 32 + (nl >> 2);
}
__global__ void k_convW(const float* __restrict__ whf, const float* __restrict__ whb,
                        const float* __restrict__ wif, const float* __restrict__ wib,
                        const float* __restrict__ bif, const float* __restrict__ bhf,
                        const float* __restrict__ bib, const float* __restrict__ bhb)
{
    {   // W_hh
        const int KQ = Hh / 4;
        size_t tot = (size_t)NPAIR * G4 * KQ;
        for (size_t i = (size_t)blockIdx.x * 256 + threadIdx.x; i < tot; i += (size_t)gridDim.x * 256) {
            int kq = (int)(i % KQ);
            size_t r = i / KQ;
            int n_il = (int)(r % G4);
            int pair = (int)(r / G4);
            int nw = pair >> 1, dir = pair & 1;
            const float* W = (dir ? whb : whf) + (size_t)nw * G4 * Hh;
            float4 v = *(const float4*)&W[(size_t)n_orig(n_il) * Hh + kq * 4];
            __half h[4] = {__float2half(v.x), __float2half(v.y),
                           __float2half(v.z), __float2half(v.w)};
            *(uint2*)&g_Whh[((size_t)pair * G4 + n_il) * Hh + kq * 4] = *(const uint2*)h;
        }
    }
    {   // W_ih
        const int KQ = Dm / 4;
        size_t tot = (size_t)NPAIR * G4 * KQ;
        for (size_t i = (size_t)blockIdx.x * 256 + threadIdx.x; i < tot; i += (size_t)gridDim.x * 256) {
            int kq = (int)(i % KQ);
            size_t r = i / KQ;
            int n_il = (int)(r % G4);
            int pair = (int)(r / G4);
            int nw = pair >> 1, dir = pair & 1;
            const float* W = (dir ? wib : wif) + (size_t)nw * G4 * Dm;
            float4 v = *(const float4*)&W[(size_t)n_orig(n_il) * Dm + kq * 4];
            __half h[4] = {__float2half(v.x), __float2half(v.y),
                           __float2half(v.z), __float2half(v.w)};
            *(uint2*)&g_Wih[((size_t)pair * G4 + n_il) * Dm + kq * 4] = *(const uint2*)h;
        }
    }
    {   // bias (interleaved)
        int tot = NPAIR * G4;
        for (int i = blockIdx.x * 256 + threadIdx.x; i < tot; i += gridDim.x * 256) {
            int n_il = i % G4, pair = i / G4;
            int nw = pair >> 1, dir = pair & 1;
            int n = n_orig(n_il);
            g_bias[i] = dir ? (bib[nw * G4 + n] + bhb[nw * G4 + n])
                            : (bif[nw * G4 + n] + bhf[nw * G4 + n]);
        }
    }
}

// ---------------- GEMM core: CTA 128x128, 8 warps (64x32 each), Kc=32, 3-stage ----
// stage layout (per stage, 20480B): A[128][32] @+0, B[128][32] @+10240.
// row stride 80B (64B data + 16B pad) -> conflict-free for LDSM and cp.async.
__device__ __forceinline__ void stage_load2(uint32_t sbase, int sidx, int c,
                                            const __half* A, const __half* B, int stride)
{
    int tid = threadIdx.x;
    int row = tid >> 1, hf = tid & 1;
    uint32_t d = sbase + sidx * STAGE_B + row * 80 + hf * 32;
    const __half* pa = A + (size_t)row * stride + c * 32 + hf * 16;
    const __half* pb = B + (size_t)row * stride + c * 32 + hf * 16;
    cp16(d, pa);           cp16(d + 16, pa + 8);
    cp16(d + 10240, pb);   cp16(d + 10256, pb + 8);
}

__device__ __forceinline__ void gemm_run(float acc[4][4][4],
                                         const __half* A, const __half* B,
                                         int stride, int nChunks, uint32_t sbase)
{
    int tid = threadIdx.x;
    int lane = tid & 31, wid = tid >> 5;
    int wm = wid >> 2, wn = wid & 3;

    uint32_t aoff[4], boff[2];
    int arow = (lane & 7) + ((lane >> 3) & 1) * 8;
    int ak = (lane >> 4) * 16;
#pragma unroll
    for (int mf = 0; mf < 4; mf++)
        aoff[mf] = (uint32_t)((wm * 64 + mf * 16 + arow) * 80 + ak);
    int brow = (lane & 7) + ((lane >> 4) & 1) * 8;
    int bk = ((lane >> 3) & 1) * 16;
#pragma unroll
    for (int j = 0; j < 2; j++)
        boff[j] = (uint32_t)((wn * 32 + j * 16 + brow) * 80 + bk + 10240);

    stage_load2(sbase, 0, 0, A, B, stride);
    cp_commit();
    stage_load2(sbase, 1, 1, A, B, stride);
    cp_commit();

    int sidx = 0;
#pragma unroll 1
    for (int c = 0; c < nChunks; c++) {
        if (c + 2 < nChunks) {
            int s2 = sidx + 2; if (s2 >= 3) s2 -= 3;
            stage_load2(sbase, s2, c + 2, A, B, stride);
            cp_commit();
            cp_wait2();
        } else if (c + 1 < nChunks) {
            cp_wait1();
        } else {
            cp_wait0();
        }
        __syncthreads();
        uint32_t sS = sbase + sidx * STAGE_B;
#pragma unroll
        for (int ks = 0; ks < 2; ks++) {
            uint32_t kb = ks * 32;
            uint32_t b[4][2];
            LDSM_X4(b[0][0], b[0][1], b[1][0], b[1][1], sS + boff[0] + kb);
            LDSM_X4(b[2][0], b[2][1], b[3][0], b[3][1], sS + boff[1] + kb);
#pragma unroll
            for (int mf = 0; mf < 4; mf++) {
                uint32_t a[4];
                LDSM_X4(a[0], a[1], a[2], a[3], sS + aoff[mf] + kb);
#pragma unroll
                for (int nf = 0; nf < 4; nf++) MMA4(acc[mf][nf], a, b[nf]);
            }
        }
        __syncthreads();
        if (++sidx >= 3) sidx = 0;
    }
}

// ---------------- kernel 4: input projection ----------------
__global__ __launch_bounds__(256, 2) void k_proj_t()
{
    int ntile = blockIdx.x, mtile = blockIdx.y, pair = blockIdx.z;
    extern __shared__ uint32_t SW[];
    uint32_t sbase = smem_u32(SW);

    float acc[4][4][4];
#pragma unroll
    for (int i = 0; i < 4; i++)
#pragma unroll
        for (int j = 0; j < 4; j++)
#pragma unroll
            for (int q = 0; q < 4; q++) acc[i][j][q] = 0.f;

    gemm_run(acc,
             g_X + (size_t)(mtile * 128) * Dm,
             g_Wih + ((size_t)pair * G4 + ntile * 128) * Dm,
             Dm, Dm / 32, sbase);

    int tid = threadIdx.x;
    int lane = tid & 31, wid = tid >> 5;
    int g = lane >> 2, t = lane & 3;
    int wm = wid >> 2, wn = wid & 3;
    int podd = t & 1;
#pragma unroll
    for (int mf = 0; mf < 4; mf++)
#pragma unroll
        for (int nf = 0; nf < 4; nf++) {
            float x = podd ? acc[mf][nf][0] : acc[mf][nf][2];
            float y = podd ? acc[mf][nf][1] : acc[mf][nf][3];
            float xr = __shfl_xor_sync(0xffffffffu, x, 1);
            float yr = __shfl_xor_sync(0xffffffffu, y, 1);
            float g0, g1, g2, g3;
            if (podd) { g0 = xr; g1 = yr; g2 = acc[mf][nf][2]; g3 = acc[mf][nf][3]; }
            else      { g0 = acc[mf][nf][0]; g1 = acc[mf][nf][1]; g2 = xr; g3 = yr; }
            int cb = wn * 32 + nf * 8 + (t & 2) * 2;
            int prow = mtile * 128 + wm * 64 + mf * 16 + g + (podd ? 8 : 0);
            float4 bz = *(const float4*)&g_bias[pair * G4 + ntile * 128 + cb];
            float4 o = {g0 + bz.x, g1 + bz.y, g2 + bz.z, g3 + bz.w};
            *(float4*)&g_P[((size_t)pair * Mtot + prow) * G4 + ntile * 128 + cb] = o;
        }
}

// ---------------- kernel 5: one LSTM step ----------------
__global__ __launch_bounds__(256, 2) void k_step_t(int s)
{
    int ntile = blockIdx.x, mtile = blockIdx.y, pair = blockIdx.z;
    int nw = pair >> 1, dir = pair & 1, w = 3 + 2 * nw;
    if (s >= w) return;
    int half = nw + 1;
    int jstep = dir ? (w - 1 - s) : s;
    int bufr = s & 1, bufw = (s + 1) & 1;

    extern __shared__ uint32_t SW[];
    uint32_t sbase = smem_u32(SW);

    float acc[4][4][4];
#pragma unroll
    for (int i = 0; i < 4; i++)
#pragma unroll
        for (int j = 0; j < 4; j++)
#pragma unroll
            for (int q = 0; q < 4; q++) acc[i][j][q] = 0.f;

    gemm_run(acc,
             g_H[bufr] + ((size_t)pair * Mtot + mtile * 128) * Hh,
             g_Whh + ((size_t)pair * G4 + ntile * 128) * Hh,
             Hh, Hh / 32, sbase);

    int tid = threadIdx.x;
    int lane = tid & 31, wid = tid >> 5;
    int g = lane >> 2, t = lane & 3;
    int wm = wid >> 2, wn = wid & 3;
    int podd = t & 1;
#pragma unroll
    for (int mf = 0; mf < 4; mf++)
#pragma unroll
        for (int nf = 0; nf < 4; nf++) {
            float x = podd ? acc[mf][nf][0] : acc[mf][nf][2];
            float y = podd ? acc[mf][nf][1] : acc[mf][nf][3];
            float xr = __shfl_xor_sync(0xffffffffu, x, 1);
            float yr = __shfl_xor_sync(0xffffffffu, y, 1);
            float g0, g1, g2, g3;
            if (podd) { g0 = xr; g1 = yr; g2 = acc[mf][nf][2]; g3 = acc[mf][nf][3]; }
            else      { g0 = acc[mf][nf][0]; g1 = acc[mf][nf][1]; g2 = xr; g3 = yr; }

            int cb = wn * 32 + nf * 8 + (t & 2) * 2;
            int hcl = cb >> 2;
            int mrow = wm * 64 + mf * 16 + g + (podd ? 8 : 0);
            int prow = mtile * 128 + mrow;
            int b = prow >> 8, l = prow & 255;
            int tpos = l - half + jstep;
            bool maskv = (tpos >= 0) && (tpos < Lseq);
            size_t hidx = ((size_t)pair * Mtot + prow) * Hh + ntile * 32 + hcl;
            if (maskv) {
                float4 pv = *(const float4*)&g_P[((size_t)pair * Mtot + (b << 8) + tpos) * G4
                                                 + ntile * 128 + cb];
                float gi = g0 + pv.x;
                float gf = g1 + pv.y;
                float gg = g2 + pv.z;
                float go = g3 + pv.w;
                float si = sigmf(gi), sf = sigmf(gf), so = sigmf(go);
                float tg = tanhfast(gg);
                float c_new = sf * g_C[hidx] + si * tg;
                float h_new = so * tanhfast(c_new);
                g_C[hidx] = c_new;
                g_H[bufw][hidx] = __float2half(h_new);
            } else {
                g_H[bufw][hidx] = g_H[bufr][hidx];
            }
        }
}

// ---------------- kernel 6: attention + residual + head ----------------
__device__ __forceinline__ float blockReduce(float v)
{
    __shared__ float sred[8];
#pragma unroll
    for (int o = 16; o > 0; o >>= 1) v += __shfl_xor_sync(0xffffffffu, v, o);
    int wid = threadIdx.x >> 5, ln = threadIdx.x & 31;
    __syncthreads();
    if (ln == 0) sred[wid] = v;
    __syncthreads();
    float r = 0.f;
    if (wid == 0) {
        r = (ln < 8) ? sred[ln] : 0.f;
#pragma unroll
        for (int o = 4; o > 0; o >>= 1) r += __shfl_xor_sync(0xffffffffu, r, o);
    }
    return r;
}

__global__ __launch_bounds__(256) void k_final(const float* __restrict__ lw,
                                               const float* __restrict__ lb,
                                               float* __restrict__ out)
{
    int p = blockIdx.x;
    int tid = threadIdx.x;
    const float* xp = g_x + (size_t)p * Dm;
    float xv[3], mv[4][3];
    __shared__ float attn_s[4];
#pragma unroll
    for (int q = 0; q < 3; q++) xv[q] = xp[tid + q * 256];

    float logits[4];
#pragma unroll
    for (int nw = 0; nw < 4; nw++) {
        size_t fo = ((size_t)(nw * 2) * Mtot + p) * Hh;
        size_t bo = ((size_t)(nw * 2 + 1) * Mtot + p) * Hh;
#pragma unroll
        for (int q = 0; q < 3; q++) {
            int d = tid + q * 256;
            float v;
            if (d < Hh)
                v = __half2float(g_H[1][fo + d]);
            else
                v = __half2float(g_H[1][bo + d - Hh]);
            mv[nw][q] = v;
        }
        float part = xv[0] * mv[nw][0] + xv[1] * mv[nw][1] + xv[2] * mv[nw][2];
        logits[nw] = blockReduce(part);
    }
    if (tid == 0) {
        float sc = rsqrtf(768.f);
        float l0 = logits[0] * sc, l1 = logits[1] * sc, l2 = logits[2] * sc, l3 = logits[3] * sc;
        float mx = fmaxf(fmaxf(l0, l1), fmaxf(l2, l3));
        float e0 = __expf(l0 - mx), e1 = __expf(l1 - mx), e2 = __expf(l2 - mx), e3 = __expf(l3 - mx);
        float inv = 1.f / (e0 + e1 + e2 + e3);
        attn_s[0] = e0 * inv; attn_s[1] = e1 * inv; attn_s[2] = e2 * inv; attn_s[3] = e3 * inv;
    }
    __syncthreads();
    float a0 = attn_s[0], a1 = attn_s[1], a2 = attn_s[2], a3 = attn_s[3];
    float ov[3];
#pragma unroll
    for (int q = 0; q < 3; q++)
        ov[q] = xv[q] + a0 * mv[0][q] + a1 * mv[1][q] + a2 * mv[2][q] + a3 * mv[3][q];

    for (int k = 0; k < 9; k++) {
        float part = 0.f;
#pragma unroll
        for (int q = 0; q < 3; q++) part += ov[q] * lw[(size_t)k * Dm + tid + q * 256];
        float tot = blockReduce(part);
        if (tid == 0) out[p * 9 + k] = tot + lb[k];
    }
}

// ---------------- launch ----------------
extern "C" void kernel_launch(void* const* d_in, const int* in_sizes, int n_in,
                              void* d_out, int out_size)
{
    const float* seq   = (const float*)d_in[0];
    const int*   valid = (const int*)d_in[1];
    const float* wif   = (const float*)d_in[2];
    const float* whf   = (const float*)d_in[3];
    const float* bif   = (const float*)d_in[4];
    const float* bhf   = (const float*)d_in[5];
    const float* wib   = (const float*)d_in[6];
    const float* whb   = (const float*)d_in[7];
    const float* bib   = (const float*)d_in[8];
    const float* bhb   = (const float*)d_in[9];
    const float* lw    = (const float*)d_in[10];
    const float* lb    = (const float*)d_in[11];
    float* out = (float*)d_out;

    cudaFuncSetAttribute(k_proj_t, cudaFuncAttributeMaxDynamicSharedMemorySize, SMEM_BYTES);
    cudaFuncSetAttribute(k_step_t, cudaFuncAttributeMaxDynamicSharedMemorySize, SMEM_BYTES);

    k_scatter<<<Bsz, 256>>>(seq, valid);
    k_convX<<<512, 256>>>();
    k_convW<<<1024, 256>>>(whf, whb, wif, wib, bif, bhf, bib, bhb);
    k_proj_t<<<dim3(NT, 8, NPAIR), 256, SMEM_BYTES>>>();
    for (int s = 0; s < 9; s++)
        k_step_t<<<dim3(NT, 8, NPAIR), 256, SMEM_BYTES>>>(s);
    k_final<<<Mtot, 256>>>(lw, lb, out);
}